// round 8
// baseline (speedup 1.0000x reference)
#include <cuda_runtime.h>
#include <cstdint>

#define B_ROWS   1024
#define D_DIM    256
#define N_TOT    100000
#define TM       128
#define TN       128
#define KCH      32
#define NCHUNK   8                       // 256 / 32
#define N_TILES  782                     // ceil(100000/128)
#define GRID_X   (N_TILES * 8)           // 6256

// padded SMEM tiles: stride 36 floats (144B) -> conflict-free fragment loads
#define SSTRIDE  36
#define TILE_B   (128 * SSTRIDE * 4)     // 18432 bytes per operand tile
#define STAGE_SZ (2 * TILE_B)            // A + B = 36864
#define SMEM_TOTAL (2 * STAGE_SZ)        // double buffered = 73728 (2 CTAs/SM)

__device__ __align__(16) float g_xn[B_ROWS * D_DIM];
__device__ __align__(16) float g_feat[(size_t)N_TOT * D_DIM];

// ---------------------------------------------------------------------------
// helpers
// ---------------------------------------------------------------------------
__device__ __forceinline__ uint32_t smem_u32(const void* p) {
    uint32_t a;
    asm("{ .reg .u64 t; cvta.to.shared.u64 t, %1; cvt.u32.u64 %0, t; }" : "=r"(a) : "l"(p));
    return a;
}

__device__ __forceinline__ void cp16(uint32_t dst, const void* src, uint32_t sz) {
    asm volatile("cp.async.cg.shared.global [%0], [%1], 16, %2;"
                 :: "r"(dst), "l"(src), "r"(sz) : "memory");
}
#define CP_COMMIT() asm volatile("cp.async.commit_group;" ::: "memory")
#define CP_WAIT_1() asm volatile("cp.async.wait_group 1;" ::: "memory")
#define CP_WAIT_0() asm volatile("cp.async.wait_group 0;" ::: "memory")

__device__ __forceinline__ float rna_tf32(float x) {
    uint32_t u;
    asm("cvt.rna.tf32.f32 %0, %1;" : "=r"(u) : "f"(x));
    return __uint_as_float(u);
}

__device__ __forceinline__ void mma_tf32(float& c0, float& c1, float& c2, float& c3,
                                         uint32_t a0, uint32_t a1, uint32_t a2, uint32_t a3,
                                         uint32_t b0, uint32_t b1) {
    asm volatile("mma.sync.aligned.m16n8k8.row.col.f32.tf32.tf32.f32 "
                 "{%0,%1,%2,%3}, {%4,%5,%6,%7}, {%8,%9}, {%0,%1,%2,%3};"
                 : "+f"(c0), "+f"(c1), "+f"(c2), "+f"(c3)
                 : "r"(a0), "r"(a1), "r"(a2), "r"(a3), "r"(b0), "r"(b1));
}

__device__ __forceinline__ void stg_cs_v2(float* p, float x, float y) {
    asm volatile("st.global.cs.v2.f32 [%0], {%1, %2};" :: "l"(p), "f"(x), "f"(y) : "memory");
}

// ---------------------------------------------------------------------------
// Kernel 1: normalize rows of inputs, round to tf32 (rna), store to g_xn
// ---------------------------------------------------------------------------
__global__ void norm_kernel(const float* __restrict__ in) {
    __shared__ float red[8];
    int r = blockIdx.x, t = threadIdx.x;
    float v = in[r * D_DIM + t];
    float s = v * v;
    #pragma unroll
    for (int o = 16; o > 0; o >>= 1) s += __shfl_xor_sync(0xFFFFFFFFu, s, o);
    if ((t & 31) == 0) red[t >> 5] = s;
    __syncthreads();
    if (t < 32) {
        float w = (t < 8) ? red[t] : 0.0f;
        #pragma unroll
        for (int o = 4; o > 0; o >>= 1) w += __shfl_xor_sync(0xFFFFFFFFu, w, o);
        if (t == 0) red[0] = rsqrtf(w);
    }
    __syncthreads();
    g_xn[r * D_DIM + t] = rna_tf32(v * red[0]);
}

// ---------------------------------------------------------------------------
// Kernel 2: round features to tf32 (rna, bias-free) into g_feat
// ---------------------------------------------------------------------------
__global__ void round_feat_kernel(const float4* __restrict__ f) {
    size_t i = (size_t)blockIdx.x * blockDim.x + threadIdx.x;
    float4 v = f[i];
    float4 o;
    o.x = rna_tf32(v.x); o.y = rna_tf32(v.y); o.z = rna_tf32(v.z); o.w = rna_tf32(v.w);
    reinterpret_cast<float4*>(g_feat)[i] = o;
}

// ---------------------------------------------------------------------------
// Kernel 3: tf32 mma.sync GEMM, tile 128x128, cp.async double buffer,
//           2 CTAs/SM for latency hiding
// ---------------------------------------------------------------------------
__device__ __forceinline__ void load_chunk(uint32_t sbase, int s, int c,
                                           int mt, int nt, int tid) {
    uint32_t astg = sbase + (uint32_t)s * STAGE_SZ;
    uint32_t bstg = astg + TILE_B;
    #pragma unroll
    for (int i = 0; i < 4; i++) {            // A: 128 rows x 8 segs of 16B
        int idx = tid + i * 256;
        int row = idx >> 3, seg = idx & 7;
        const float* src = g_xn + ((mt * TM + row) * D_DIM + c * KCH + seg * 4);
        cp16(astg + (uint32_t)(row * (SSTRIDE * 4) + seg * 16), src, 16u);
    }
    #pragma unroll
    for (int i = 0; i < 4; i++) {            // B: 128 feature rows (zero-fill OOB)
        int idx = tid + i * 256;
        int row = idx >> 3, seg = idx & 7;
        int gn = nt * TN + row;
        int gc = (gn < N_TOT) ? gn : 0;
        uint32_t sz = (gn < N_TOT) ? 16u : 0u;
        const float* src = g_feat + ((size_t)gc * D_DIM + c * KCH + seg * 4);
        cp16(bstg + (uint32_t)(row * (SSTRIDE * 4) + seg * 16), src, sz);
    }
    CP_COMMIT();
}

__global__ void __launch_bounds__(256, 2) gemm_kernel(float* __restrict__ out) {
    extern __shared__ float smem[];
    uint32_t sbase = smem_u32(smem);
    int tid = threadIdx.x, wid = tid >> 5, lane = tid & 31;
    int lr = lane >> 2, lc = lane & 3;
    int bx = blockIdx.x;
    int nt = bx >> 3;                    // 8 consecutive CTAs share a feature tile
    int mt = bx & 7;
    int wm = wid >> 1, wn = wid & 1;     // 4 x 2 warp grid, warp tile 32m x 64n

    float acc[2][8][4];
    #pragma unroll
    for (int i = 0; i < 2; i++)
        #pragma unroll
        for (int j = 0; j < 8; j++)
            #pragma unroll
            for (int k = 0; k < 4; k++) acc[i][j][k] = 0.0f;

    load_chunk(sbase, 0, 0, mt, nt, tid);
    load_chunk(sbase, 1, 1, mt, nt, tid);

    // per-warp SMEM base offsets (floats), hoisted out of the k-loop
    int a_base0 = (wm * 32 + lr) * SSTRIDE + lc;            // mi=0 row
    int b_base  = (wn * 64 + lr) * SSTRIDE + lc;            // ni=0 col

    for (int c = 0; c < NCHUNK; c++) {
        int s = c & 1;
        if (c < NCHUNK - 1) CP_WAIT_1(); else CP_WAIT_0();
        __syncthreads();

        const float* As = smem + (size_t)s * (STAGE_SZ / 4);
        const float* Bs = As + (TILE_B / 4);
        const float* Ap = As + a_base0;
        const float* Bp = Bs + b_base;

        #pragma unroll
        for (int ks = 0; ks < 4; ks++) {
            int kb = ks * 8;
            uint32_t af[2][4];
            #pragma unroll
            for (int mi = 0; mi < 2; mi++) {
                const float* ap = Ap + mi * 16 * SSTRIDE + kb;
                af[mi][0] = __float_as_uint(ap[0]);
                af[mi][1] = __float_as_uint(ap[8 * SSTRIDE]);
                af[mi][2] = __float_as_uint(ap[4]);
                af[mi][3] = __float_as_uint(ap[8 * SSTRIDE + 4]);
            }
            #pragma unroll
            for (int ni = 0; ni < 8; ni++) {
                const float* bp = Bp + ni * 8 * SSTRIDE + kb;
                uint32_t b0 = __float_as_uint(bp[0]);
                uint32_t b1 = __float_as_uint(bp[4]);
                #pragma unroll
                for (int mi = 0; mi < 2; mi++)
                    mma_tf32(acc[mi][ni][0], acc[mi][ni][1], acc[mi][ni][2], acc[mi][ni][3],
                             af[mi][0], af[mi][1], af[mi][2], af[mi][3], b0, b1);
            }
        }

        __syncthreads();                 // stage s fully consumed before refill
        if (c + 2 < NCHUNK) load_chunk(sbase, s, c + 2, mt, nt, tid);
    }

    // epilogue: scale by 1/TEMP, streaming stores (write-once data, evict-first)
    #pragma unroll
    for (int mi = 0; mi < 2; mi++) {
        size_t row = (size_t)(mt * TM + wm * 32 + mi * 16 + lr);
        float* orow0 = out + row * N_TOT;
        float* orow1 = orow0 + (size_t)8 * N_TOT;
        #pragma unroll
        for (int ni = 0; ni < 8; ni++) {
            int col = nt * TN + wn * 64 + ni * 8 + 2 * lc;
            if (col < N_TOT) {           // whole 8-col group valid or not (100000 % 8 == 0)
                stg_cs_v2(orow0 + col, acc[mi][ni][0] * 20.0f, acc[mi][ni][1] * 20.0f);
                stg_cs_v2(orow1 + col, acc[mi][ni][2] * 20.0f, acc[mi][ni][3] * 20.0f);
            }
        }
    }
}

// ---------------------------------------------------------------------------
extern "C" void kernel_launch(void* const* d_in, const int* in_sizes, int n_in,
                              void* d_out, int out_size) {
    const float* inputs   = (const float*)d_in[0];   // [1024, 256]  float32
    const float* features = (const float*)d_in[2];   // [100000, 256] float32
    float* out = (float*)d_out;                      // [1024, 100000] float32

    cudaFuncSetAttribute(gemm_kernel, cudaFuncAttributeMaxDynamicSharedMemorySize, SMEM_TOTAL);

    norm_kernel<<<B_ROWS, D_DIM>>>(inputs);
    round_feat_kernel<<<(N_TOT * D_DIM / 4) / 256, 256>>>((const float4*)features);
    gemm_kernel<<<GRID_X, 256, SMEM_TOTAL>>>(out);
}

// round 9
// speedup vs baseline: 1.6661x; 1.6661x over previous
#include <cuda_runtime.h>
#include <cuda_fp16.h>
#include <cstdint>

#define B_ROWS   1024
#define D_DIM    256
#define N_TOT    100000
#define TM       128
#define TN       128
#define KCH      32
#define NCHUNK   8                        // 256 / 32
#define N_TILES  782                      // ceil(100000/128)
#define GRID_X   (N_TILES * 8)            // 6256

// fp16 tiles, padded row stride 40 halves (80 B) -> ldmatrix conflict-free
#define RSTRIDE_H  40
#define TILE_BYTES (128 * RSTRIDE_H * 2)  // 10240 per operand tile
#define STAGE_SZ   (2 * TILE_BYTES)       // A + B = 20480
#define SMEM_TOTAL (2 * STAGE_SZ)         // double buffered = 40960

__device__ __align__(16) __half g_xn[B_ROWS * D_DIM];
__device__ __align__(16) __half g_feat[(size_t)N_TOT * D_DIM];

// ---------------------------------------------------------------------------
// helpers
// ---------------------------------------------------------------------------
__device__ __forceinline__ uint32_t smem_u32(const void* p) {
    uint32_t a;
    asm("{ .reg .u64 t; cvta.to.shared.u64 t, %1; cvt.u32.u64 %0, t; }" : "=r"(a) : "l"(p));
    return a;
}

__device__ __forceinline__ void cp16(uint32_t dst, const void* src, uint32_t sz) {
    asm volatile("cp.async.cg.shared.global [%0], [%1], 16, %2;"
                 :: "r"(dst), "l"(src), "r"(sz) : "memory");
}
#define CP_COMMIT() asm volatile("cp.async.commit_group;" ::: "memory")
#define CP_WAIT_1() asm volatile("cp.async.wait_group 1;" ::: "memory")
#define CP_WAIT_0() asm volatile("cp.async.wait_group 0;" ::: "memory")

__device__ __forceinline__ void ldsm_x4(uint32_t* r, uint32_t addr) {
    asm volatile("ldmatrix.sync.aligned.m8n8.x4.shared.b16 {%0,%1,%2,%3}, [%4];"
                 : "=r"(r[0]), "=r"(r[1]), "=r"(r[2]), "=r"(r[3]) : "r"(addr));
}

__device__ __forceinline__ void mma_f16(float& c0, float& c1, float& c2, float& c3,
                                        uint32_t a0, uint32_t a1, uint32_t a2, uint32_t a3,
                                        uint32_t b0, uint32_t b1) {
    asm volatile("mma.sync.aligned.m16n8k16.row.col.f32.f16.f16.f32 "
                 "{%0,%1,%2,%3}, {%4,%5,%6,%7}, {%8,%9}, {%0,%1,%2,%3};"
                 : "+f"(c0), "+f"(c1), "+f"(c2), "+f"(c3)
                 : "r"(a0), "r"(a1), "r"(a2), "r"(a3), "r"(b0), "r"(b1));
}

__device__ __forceinline__ void stg_cs_v2(float* p, float x, float y) {
    asm volatile("st.global.cs.v2.f32 [%0], {%1, %2};" :: "l"(p), "f"(x), "f"(y) : "memory");
}

// ---------------------------------------------------------------------------
// Kernel 1: normalize rows of inputs (fp32 math), store fp16 (rne)
// ---------------------------------------------------------------------------
__global__ void norm_kernel(const float* __restrict__ in) {
    __shared__ float red[8];
    int r = blockIdx.x, t = threadIdx.x;
    float v = in[r * D_DIM + t];
    float s = v * v;
    #pragma unroll
    for (int o = 16; o > 0; o >>= 1) s += __shfl_xor_sync(0xFFFFFFFFu, s, o);
    if ((t & 31) == 0) red[t >> 5] = s;
    __syncthreads();
    if (t < 32) {
        float w = (t < 8) ? red[t] : 0.0f;
        #pragma unroll
        for (int o = 4; o > 0; o >>= 1) w += __shfl_xor_sync(0xFFFFFFFFu, w, o);
        if (t == 0) red[0] = rsqrtf(w);
    }
    __syncthreads();
    g_xn[r * D_DIM + t] = __float2half_rn(v * red[0]);
}

// ---------------------------------------------------------------------------
// Kernel 2: convert features to fp16 (rne) into g_feat
// ---------------------------------------------------------------------------
__global__ void conv_feat_kernel(const float4* __restrict__ f) {
    size_t i = (size_t)blockIdx.x * blockDim.x + threadIdx.x;   // one float4 each
    float4 v = f[i];
    __half2 h0 = __floats2half2_rn(v.x, v.y);
    __half2 h1 = __floats2half2_rn(v.z, v.w);
    uint2 pk;
    pk.x = *reinterpret_cast<uint32_t*>(&h0);
    pk.y = *reinterpret_cast<uint32_t*>(&h1);
    reinterpret_cast<uint2*>(g_feat)[i] = pk;
}

// ---------------------------------------------------------------------------
// Kernel 3: fp16 mma.sync GEMM (m16n8k16), tile 128x128, cp.async dbl buffer
// ---------------------------------------------------------------------------
__device__ __forceinline__ void load_chunk(uint32_t sbase, int s, int c,
                                           int mt, int nt, int tid) {
    uint32_t astg = sbase + (uint32_t)s * STAGE_SZ;
    uint32_t bstg = astg + TILE_BYTES;
    #pragma unroll
    for (int i = 0; i < 2; i++) {            // A: 128 rows x 4 segs of 16B (8 halves)
        int idx = tid + i * 256;
        int row = idx >> 2, seg = idx & 3;
        const __half* src = g_xn + ((mt * TM + row) * D_DIM + c * KCH + seg * 8);
        cp16(astg + (uint32_t)(row * (RSTRIDE_H * 2) + seg * 16), src, 16u);
    }
    #pragma unroll
    for (int i = 0; i < 2; i++) {            // B: 128 feature rows (zero-fill OOB)
        int idx = tid + i * 256;
        int row = idx >> 2, seg = idx & 3;
        int gn = nt * TN + row;
        int gc = (gn < N_TOT) ? gn : 0;
        uint32_t sz = (gn < N_TOT) ? 16u : 0u;
        const __half* src = g_feat + ((size_t)gc * D_DIM + c * KCH + seg * 8);
        cp16(bstg + (uint32_t)(row * (RSTRIDE_H * 2) + seg * 16), src, sz);
    }
    CP_COMMIT();
}

__global__ void __launch_bounds__(256, 2) gemm_kernel(float* __restrict__ out) {
    extern __shared__ float smem[];
    uint32_t sbase = smem_u32(smem);
    int tid = threadIdx.x, wid = tid >> 5, lane = tid & 31;
    int lr = lane >> 2, lc = lane & 3;
    int bx = blockIdx.x;
    int nt = bx >> 3;                    // 8 consecutive CTAs share a feature tile
    int mt = bx & 7;
    int wm = wid >> 1, wn = wid & 1;     // 4 x 2 warp grid, warp tile 32m x 64n

    float acc[2][8][4];
    #pragma unroll
    for (int i = 0; i < 2; i++)
        #pragma unroll
        for (int j = 0; j < 8; j++)
            #pragma unroll
            for (int k = 0; k < 4; k++) acc[i][j][k] = 0.0f;

    load_chunk(sbase, 0, 0, mt, nt, tid);
    load_chunk(sbase, 1, 1, mt, nt, tid);

    // ldmatrix lane addresses (byte offsets within operand tile)
    // A x4: m0=rows0-7/k0-7, m1=rows8-15/k0-7, m2=rows0-7/k8-15, m3=rows8-15/k8-15
    uint32_t a_off[2];
    #pragma unroll
    for (int mi = 0; mi < 2; mi++) {
        int row = wm * 32 + mi * 16 + (lane & 7) + ((lane >> 3) & 1) * 8;
        a_off[mi] = (uint32_t)((row * RSTRIDE_H + (lane >> 4) * 8) * 2);
    }
    // B x4 (pair of n8 blocks): m0=n0-7/k0-7, m1=n0-7/k8-15, m2=n8-15/k0-7, m3=n8-15/k8-15
    uint32_t b_off[4];
    #pragma unroll
    for (int j = 0; j < 4; j++) {
        int row = wn * 64 + j * 16 + (lane & 7) + ((lane >> 4) & 1) * 8;
        b_off[j] = (uint32_t)((row * RSTRIDE_H + ((lane >> 3) & 1) * 8) * 2);
    }

    for (int c = 0; c < NCHUNK; c++) {
        int s = c & 1;
        if (c < NCHUNK - 1) CP_WAIT_1(); else CP_WAIT_0();
        __syncthreads();

        uint32_t astg = sbase + (uint32_t)s * STAGE_SZ;
        uint32_t bstg = astg + TILE_BYTES;

        #pragma unroll
        for (int ks = 0; ks < 2; ks++) {     // two k16 steps per 32-K chunk
            uint32_t koff = (uint32_t)(ks * 16 * 2);   // 16 halves = 32 B
            uint32_t af[2][4], bf[4][4];
            #pragma unroll
            for (int mi = 0; mi < 2; mi++) ldsm_x4(af[mi], astg + a_off[mi] + koff);
            #pragma unroll
            for (int j = 0; j < 4; j++)    ldsm_x4(bf[j], bstg + b_off[j] + koff);

            #pragma unroll
            for (int ni = 0; ni < 8; ni++) {
                uint32_t b0 = bf[ni >> 1][(ni & 1) * 2 + 0];
                uint32_t b1 = bf[ni >> 1][(ni & 1) * 2 + 1];
                #pragma unroll
                for (int mi = 0; mi < 2; mi++)
                    mma_f16(acc[mi][ni][0], acc[mi][ni][1], acc[mi][ni][2], acc[mi][ni][3],
                            af[mi][0], af[mi][1], af[mi][2], af[mi][3], b0, b1);
            }
        }

        __syncthreads();                 // stage s fully consumed before refill
        if (c + 2 < NCHUNK) load_chunk(sbase, s, c + 2, mt, nt, tid);
    }

    // epilogue: scale by 1/TEMP, streaming stores (write-once data)
    #pragma unroll
    for (int mi = 0; mi < 2; mi++) {
        size_t row = (size_t)(mt * TM + wm * 32 + mi * 16 + lr);
        float* orow0 = out + row * N_TOT;
        float* orow1 = orow0 + (size_t)8 * N_TOT;
        #pragma unroll
        for (int ni = 0; ni < 8; ni++) {
            int col = nt * TN + wn * 64 + ni * 8 + 2 * lc;
            if (col < N_TOT) {           // whole 8-col group valid or not (100000 % 8 == 0)
                stg_cs_v2(orow0 + col, acc[mi][ni][0] * 20.0f, acc[mi][ni][1] * 20.0f);
                stg_cs_v2(orow1 + col, acc[mi][ni][2] * 20.0f, acc[mi][ni][3] * 20.0f);
            }
        }
    }
}

// ---------------------------------------------------------------------------
extern "C" void kernel_launch(void* const* d_in, const int* in_sizes, int n_in,
                              void* d_out, int out_size) {
    const float* inputs   = (const float*)d_in[0];   // [1024, 256]  float32
    const float* features = (const float*)d_in[2];   // [100000, 256] float32
    float* out = (float*)d_out;                      // [1024, 100000] float32

    norm_kernel<<<B_ROWS, D_DIM>>>(inputs);
    conv_feat_kernel<<<(N_TOT * D_DIM / 4) / 256, 256>>>((const float4*)features);
    gemm_kernel<<<GRID_X, 256, SMEM_TOTAL>>>(out);
}